// round 15
// baseline (speedup 1.0000x reference)
#include <cuda_runtime.h>
#include <math.h>

#define Cn 4096
#define Vn 32000
#define Hn 256
#define Dn 128
#define Nb 16
#define Tt 256
#define NBLK 128

// ---------------- device scratch (static) ----------------
__device__ float g_t1[Cn * Hn];
__device__ float g_f1[Cn * Hn];
__device__ float g_t2[Cn * Hn];
__device__ float g_ft[Cn * Hn];
__device__ float g_Eyn[Cn * Dn];       // features of next_state_emb
__device__ float g_Exn[Cn * Dn];       // features of state_emb (row-normalized: ExnN·Sn = 1)
__device__ float g_Ext[Cn * Dn];       // features of terminal-MLP out (row-normalized by Se)
__device__ float g_Ele[Vn * Dn];       // features of terminal_emb
__device__ float g_Sn[Dn];
__device__ float g_Se[Dn];
__device__ float g_Exs[Dn];
__device__ float g_part[NBLK][Nb * Dn]; // stage-1 per-block partial G'
__device__ float g_fin[2][Nb * Dn];     // double-buffered final G state
__device__ unsigned g_flag[NBLK * 8];   // per-block barrier flags (32B stride)

// ---------------- zero / reset ----------------
__global__ __launch_bounds__(256) void kzero() {
    int i = threadIdx.x;
    if (i < Dn) { g_Sn[i] = 0.f; g_Se[i] = 0.f; }
    for (int j = i; j < NBLK * 8; j += 256) g_flag[j] = 0u;
}

// ------------- generic tiled GEMM: Out = epi(A[M,K]@W[K,N]) -------------
// mode 1: relu(+bias); 2: relu(+bias)+R; 3: l2-normalize-A-rows then exp(x-0.5)
__global__ __launch_bounds__(256) void kgemm(const float* __restrict__ A,
                                             const float* __restrict__ W,
                                             const float* __restrict__ bias,
                                             const float* __restrict__ R,
                                             float* __restrict__ Out,
                                             int M, int N, int K, int mode) {
    __shared__ float As[16][68];
    __shared__ float Ws[16][68];
    int tid = threadIdx.x;
    int m0 = blockIdx.x * 64, n0 = blockIdx.y * 64;
    int ar = tid >> 2, ak = (tid & 3) * 4;
    int wk = tid >> 4, wn = (tid & 15) * 4;
    int ty = tid >> 4, tx = tid & 15;
    float acc[4][4] = {};
    float ss[4] = {};   // row sum-of-squares (mode 3)
    for (int kt = 0; kt < K; kt += 16) {
        float4 av = *(const float4*)(A + (size_t)(m0 + ar) * K + kt + ak);
        As[ak + 0][ar] = av.x; As[ak + 1][ar] = av.y;
        As[ak + 2][ar] = av.z; As[ak + 3][ar] = av.w;
        *(float4*)&Ws[wk][wn] = *(const float4*)(W + (size_t)(kt + wk) * N + n0 + wn);
        __syncthreads();
#pragma unroll
        for (int k = 0; k < 16; k++) {
            float a[4], b[4];
            *(float4*)a = *(const float4*)&As[k][ty * 4];
            *(float4*)b = *(const float4*)&Ws[k][tx * 4];
            if (mode == 3) {
#pragma unroll
                for (int i = 0; i < 4; i++) ss[i] += a[i] * a[i];
            }
#pragma unroll
            for (int i = 0; i < 4; i++)
#pragma unroll
                for (int j = 0; j < 4; j++) acc[i][j] += a[i] * b[j];
        }
        __syncthreads();
    }
#pragma unroll
    for (int i = 0; i < 4; i++) {
        int m = m0 + ty * 4 + i;
        float rs = (mode == 3) ? rsqrtf(ss[i]) : 1.f;
#pragma unroll
        for (int j = 0; j < 4; j++) {
            int n = n0 + tx * 4 + j;
            float v = acc[i][j];
            if (mode == 1 || mode == 2) v = fmaxf(v + bias[n], 0.f);
            if (mode == 2) v += R[(size_t)m * N + n];
            if (mode == 3) v = expf(v * rs - 0.5f);
            Out[(size_t)m * N + n] = v;
        }
    }
}

// ------------- column sums -------------
__global__ __launch_bounds__(128) void kcolsum(const float* __restrict__ E, int rows,
                                               float* __restrict__ S) {
    int d = threadIdx.x;
    float acc = 0.f;
    for (int r = blockIdx.x; r < rows; r += gridDim.x) acc += E[(size_t)r * Dn + d];
    atomicAdd(&S[d], acc);
}

// ------------- row normalize: E[r,:] /= (E[r,:]·S) -------------
__global__ __launch_bounds__(128) void krowdiv(float* __restrict__ E,
                                               const float* __restrict__ S) {
    int r = blockIdx.x, tid = threadIdx.x;
    __shared__ float red[4];
    float v = E[(size_t)r * Dn + tid];
    float p = v * S[tid];
#pragma unroll
    for (int o = 16; o; o >>= 1) p += __shfl_xor_sync(~0u, p, o);
    if ((tid & 31) == 0) red[tid >> 5] = p;
    __syncthreads();
    float u = red[0] + red[1] + red[2] + red[3];
    E[(size_t)r * Dn + tid] = v / u;
}

// ------------- start MLP + features of the single start vector -------------
__global__ __launch_bounds__(256) void kstartmlp(
    const float* se, const float* w0, const float* b0,
    const float* w1, const float* b1, const float* w2, const float* b2,
    const float* w3, const float* b3, const float* w4, const float* b4,
    const float* proj) {
    __shared__ float xs[256], Ab[256], Bb[256], Cb[256];
    __shared__ float red[8], sinv;
    int tid = threadIdx.x;
    xs[tid] = se[tid];
    __syncthreads();
    float acc = 0.f;
    for (int i = 0; i < 256; i++) acc += xs[i] * w0[i * 256 + tid];
    Ab[tid] = acc + b0[tid];
    __syncthreads();
    acc = 0.f;
    for (int i = 0; i < 256; i++) acc += Ab[i] * w1[i * 256 + tid];
    Bb[tid] = fmaxf(acc + b1[tid], 0.f);
    __syncthreads();
    acc = 0.f;
    for (int i = 0; i < 256; i++) acc += Bb[i] * w2[i * 256 + tid];
    Cb[tid] = fmaxf(acc + b2[tid], 0.f) + Ab[tid];
    __syncthreads();
    acc = 0.f;
    for (int i = 0; i < 256; i++) acc += Cb[i] * w3[i * 256 + tid];
    __syncthreads();
    Bb[tid] = fmaxf(acc + b3[tid], 0.f);
    __syncthreads();
    acc = 0.f;
    for (int i = 0; i < 256; i++) acc += Bb[i] * w4[i * 256 + tid];
    Ab[tid] = fmaxf(acc + b4[tid], 0.f) + Cb[tid];
    __syncthreads();
    float ss = Ab[tid] * Ab[tid];
#pragma unroll
    for (int o = 16; o; o >>= 1) ss += __shfl_xor_sync(~0u, ss, o);
    if ((tid & 31) == 0) red[tid >> 5] = ss;
    __syncthreads();
    if (tid == 0) {
        float t = 0.f;
        for (int i = 0; i < 8; i++) t += red[i];
        sinv = rsqrtf(t);
    }
    __syncthreads();
    if (tid < 128) {
        float a2 = 0.f;
        for (int i = 0; i < 256; i++) a2 += Ab[i] * proj[i * 128 + tid];
        g_Exs[tid] = expf(a2 * sinv - 0.5f);
    }
}

// =========== persistent recursion kernel: all 256 HMM steps ===========
// Two flag barriers per step; G' reduced in two stages (no atomics).
#define GB_ARRIVE()                                                            \
    do {                                                                       \
        __threadfence();                                                       \
        __syncthreads();                                                       \
        if (tid == 0) *(volatile unsigned*)&g_flag[blk * 8] = want;            \
    } while (0)
#define GB_POLL()                                                              \
    do {                                                                       \
        if (tid < NBLK) {                                                      \
            volatile unsigned* fl = &g_flag[tid * 8];                          \
            while (*fl < want) __nanosleep(32);                                \
        }                                                                      \
        __syncthreads();                                                       \
        want++;                                                                \
    } while (0)

__global__ __launch_bounds__(256, 1) void krec(const int* __restrict__ text,
                                               float* __restrict__ out) {
    __shared__ float Gs[Nb][Dn];
    __shared__ float Egs[Nb][Dn];
    __shared__ float Ash[Nb][32];
    __shared__ float zsh[Nb];
    __shared__ float snS[Dn];
    int tid = threadIdx.x;
    int blk = blockIdx.x;
    int w = tid >> 5, lane = tid & 31;
    int cl = tid >> 3, q = tid & 7;
    int dd = tid & 127, half = tid >> 7;
    unsigned want = 1;

    // persistent operands: thread owns d-chunks {j*32 + q*4 .. +3} of its state row
    float a[16], b[16], xn[32];
    {
        const float4* ap = (const float4*)(g_Ext + (size_t)(blk * 32 + cl) * Dn + q * 4);
        const float4* bp = (const float4*)(g_Eyn + (size_t)(blk * 32 + cl) * Dn + q * 4);
#pragma unroll
        for (int j = 0; j < 4; j++) {
            *(float4*)&a[j * 4] = ap[j * 8];   // stride 32 floats = 8 float4
            *(float4*)&b[j * 4] = bp[j * 8];
        }
#pragma unroll
        for (int k = 0; k < 32; k++) xn[k] = g_Exn[(size_t)(blk * 32 + k) * Dn + dd];
    }
    if (tid < Dn) snS[tid] = g_Sn[tid];

    // init final buffer 0: Exs replicated across all 16 batches
    if (tid < 16) {
        int ib = blk * 16 + tid;
        __stcg(&g_fin[0][ib], g_Exs[ib & 127]);
    }
    float evAcc = 0.f;

    GB_ARRIVE();
    GB_POLL();

    // prefetch token features for t=0
    float egv[8];
#pragma unroll
    for (int k = 0; k < 8; k++) {
        int i = k * 256 + tid, n = i >> 7, d = i & 127;
        int tk = __ldg(&text[n * Tt + 0]);
        egv[k] = __ldg(&g_Ele[(size_t)tk * Dn + d]);
    }

    for (int t = 0; t < Tt; t++) {
        const float* Gcur = g_fin[t & 1];

        // z[n] = G[n,:]·Sn ; ghat = G/z  (warp w owns batches w and w+8)
        {
            float4 ga = __ldcg((const float4*)(Gcur + w * Dn + lane * 4));
            float4 gb = __ldcg((const float4*)(Gcur + (w + 8) * Dn + lane * 4));
            float4 s4 = *(const float4*)&snS[lane * 4];
            float za = ga.x * s4.x + ga.y * s4.y + ga.z * s4.z + ga.w * s4.w;
            float zb = gb.x * s4.x + gb.y * s4.y + gb.z * s4.z + gb.w * s4.w;
#pragma unroll
            for (int o = 16; o; o >>= 1) {
                za += __shfl_xor_sync(~0u, za, o);
                zb += __shfl_xor_sync(~0u, zb, o);
            }
            if (lane == 0) { zsh[w] = za; zsh[w + 8] = zb; }
            float ia = 1.f / za, ib2 = 1.f / zb;
            ga.x *= ia; ga.y *= ia; ga.z *= ia; ga.w *= ia;
            gb.x *= ib2; gb.y *= ib2; gb.z *= ib2; gb.w *= ib2;
            *(float4*)&Gs[w][lane * 4] = ga;
            *(float4*)&Gs[w + 8][lane * 4] = gb;
        }
        // stage token features
#pragma unroll
        for (int k = 0; k < 8; k++) ((float*)Egs)[k * 256 + tid] = egv[k];
        __syncthreads();
        if (blk == 0 && tid < 16 && t > 0) evAcc += logf(zsh[tid]);

        // A[n,c] = (ExtN_c·Ele_n) * (ghat_n·Eyn_c)
#pragma unroll
        for (int n = 0; n < Nb; n++) {
            float eo = 0.f, mo = 0.f;
#pragma unroll
            for (int j = 0; j < 4; j++) {
                float4 e = *(const float4*)&Egs[n][j * 32 + q * 4];
                float4 g = *(const float4*)&Gs[n][j * 32 + q * 4];
                eo += a[j*4]*e.x + a[j*4+1]*e.y + a[j*4+2]*e.z + a[j*4+3]*e.w;
                mo += b[j*4]*g.x + b[j*4+1]*g.y + b[j*4+2]*g.z + b[j*4+3]*g.w;
            }
#pragma unroll
            for (int o = 4; o; o >>= 1) {
                eo += __shfl_xor_sync(~0u, eo, o);
                mo += __shfl_xor_sync(~0u, mo, o);
            }
            if (q == 0) Ash[n][cl] = eo * mo;
        }
        __syncthreads();

        // stage 1: per-block partial G' -> private slot (coalesced, no atomics)
#pragma unroll
        for (int k = 0; k < 8; k++) {
            int n = 2 * k + half;
            float acc = 0.f;
            const float* arow = Ash[n];
#pragma unroll
            for (int c2 = 0; c2 < 32; c2++) acc += arow[c2] * xn[c2];
            __stcg(&g_part[blk][n * Dn + dd], acc);
        }

        GB_ARRIVE();
        // prefetch next step's token features under the barrier window
        if (t + 1 < Tt) {
#pragma unroll
            for (int k = 0; k < 8; k++) {
                int i = k * 256 + tid, n = i >> 7, d = i & 127;
                int tk = __ldg(&text[n * Tt + t + 1]);
                egv[k] = __ldg(&g_Ele[(size_t)tk * Dn + d]);
            }
        }
        GB_POLL();

        // stage 2: block reduces its 16 outputs over the 128 partials
        {
            int j = tid >> 4, s = tid & 15;
            int o = blk * 16 + j;
            float p = 0.f;
#pragma unroll
            for (int i = 0; i < 8; i++) p += __ldcg(&g_part[s * 8 + i][o]);
#pragma unroll
            for (int m = 8; m; m >>= 1) p += __shfl_xor_sync(~0u, p, m);
            if (s == 0) __stcg(&g_fin[(t + 1) & 1][o], p);
        }

        GB_ARRIVE();
        GB_POLL();
    }

    // finalize: block 0 adds log Z of the last state and reduces evidence
    if (blk == 0) {
        const float* Gf = g_fin[Tt & 1];
        float4 ga = __ldcg((const float4*)(Gf + w * Dn + lane * 4));
        float4 gb = __ldcg((const float4*)(Gf + (w + 8) * Dn + lane * 4));
        float4 s4 = *(const float4*)&snS[lane * 4];
        float za = ga.x * s4.x + ga.y * s4.y + ga.z * s4.z + ga.w * s4.w;
        float zb = gb.x * s4.x + gb.y * s4.y + gb.z * s4.z + gb.w * s4.w;
#pragma unroll
        for (int o = 16; o; o >>= 1) {
            za += __shfl_xor_sync(~0u, za, o);
            zb += __shfl_xor_sync(~0u, zb, o);
        }
        if (lane == 0) { zsh[w] = za; zsh[w + 8] = zb; }
        __syncthreads();
        if (tid < 16) evAcc += logf(zsh[tid]);
        if (w == 0) {
#pragma unroll
            for (int o = 8; o; o >>= 1) evAcc += __shfl_xor_sync(~0u, evAcc, o);
            if (tid == 0) out[0] = evAcc;
        }
    }
}

extern "C" void kernel_launch(void* const* d_in, const int* in_sizes, int n_in,
                              void* d_out, int out_size) {
    (void)n_in; (void)out_size;
    const float *se, *sw0, *sb0, *sw1, *sb1, *sw2, *sb2, *sw3, *sb3, *sw4, *sb4;
    const float *state_emb, *next_state_emb, *pre_emb;
    const float *tw1, *tb1, *tw2, *tb2, *tw3, *tb3, *tw4, *tb4, *term_emb, *proj;
    const int* text;
    if (in_sizes[0] == Hn) {
        se  = (const float*)d_in[0];
        sw0 = (const float*)d_in[1];  sb0 = (const float*)d_in[2];
        sw1 = (const float*)d_in[3];  sb1 = (const float*)d_in[4];
        sw2 = (const float*)d_in[5];  sb2 = (const float*)d_in[6];
        sw3 = (const float*)d_in[7];  sb3 = (const float*)d_in[8];
        sw4 = (const float*)d_in[9];  sb4 = (const float*)d_in[10];
        state_emb = (const float*)d_in[11];
        next_state_emb = (const float*)d_in[12];
        pre_emb = (const float*)d_in[13];
        tw1 = (const float*)d_in[14]; tb1 = (const float*)d_in[15];
        tw2 = (const float*)d_in[16]; tb2 = (const float*)d_in[17];
        tw3 = (const float*)d_in[18]; tb3 = (const float*)d_in[19];
        tw4 = (const float*)d_in[20]; tb4 = (const float*)d_in[21];
        term_emb = (const float*)d_in[22];
        proj = (const float*)d_in[23];
        text = (const int*)d_in[24];
    } else {
        text = (const int*)d_in[0];
        se  = (const float*)d_in[2];
        sw0 = (const float*)d_in[3];  sb0 = (const float*)d_in[4];
        sw1 = (const float*)d_in[5];  sb1 = (const float*)d_in[6];
        sw2 = (const float*)d_in[7];  sb2 = (const float*)d_in[8];
        sw3 = (const float*)d_in[9];  sb3 = (const float*)d_in[10];
        sw4 = (const float*)d_in[11]; sb4 = (const float*)d_in[12];
        tw1 = (const float*)d_in[13]; tb1 = (const float*)d_in[14];
        tw2 = (const float*)d_in[15]; tb2 = (const float*)d_in[16];
        tw3 = (const float*)d_in[17]; tb3 = (const float*)d_in[18];
        tw4 = (const float*)d_in[19]; tb4 = (const float*)d_in[20];
        state_emb = (const float*)d_in[21];
        next_state_emb = (const float*)d_in[22];
        pre_emb = (const float*)d_in[23];
        term_emb = (const float*)d_in[24];
        proj = (const float*)d_in[25];
    }

    float *pT1, *pF1, *pT2, *pFt, *pEyn, *pExn, *pExt, *pEle, *pSn, *pSe;
    cudaGetSymbolAddress((void**)&pT1, g_t1);
    cudaGetSymbolAddress((void**)&pF1, g_f1);
    cudaGetSymbolAddress((void**)&pT2, g_t2);
    cudaGetSymbolAddress((void**)&pFt, g_ft);
    cudaGetSymbolAddress((void**)&pEyn, g_Eyn);
    cudaGetSymbolAddress((void**)&pExn, g_Exn);
    cudaGetSymbolAddress((void**)&pExt, g_Ext);
    cudaGetSymbolAddress((void**)&pEle, g_Ele);
    cudaGetSymbolAddress((void**)&pSn, g_Sn);
    cudaGetSymbolAddress((void**)&pSe, g_Se);

    kzero<<<1, 256>>>();

    // terminal MLP: two ResLayers on preterminal_emb
    kgemm<<<dim3(Cn / 64, 4), 256>>>(pre_emb, tw1, tb1, nullptr, pT1, Cn, Hn, Hn, 1);
    kgemm<<<dim3(Cn / 64, 4), 256>>>(pT1, tw2, tb2, pre_emb, pF1, Cn, Hn, Hn, 2);
    kgemm<<<dim3(Cn / 64, 4), 256>>>(pF1, tw3, tb3, nullptr, pT2, Cn, Hn, Hn, 1);
    kgemm<<<dim3(Cn / 64, 4), 256>>>(pT2, tw4, tb4, pF1, pFt, Cn, Hn, Hn, 2);

    // features (mode 3 = fused row-l2norm + exp(x-0.5))
    kgemm<<<dim3(Cn / 64, 2), 256>>>(next_state_emb, proj, nullptr, nullptr, pEyn, Cn, Dn, Hn, 3);
    kcolsum<<<256, 128>>>(pEyn, Cn, pSn);

    kgemm<<<dim3(Cn / 64, 2), 256>>>(state_emb, proj, nullptr, nullptr, pExn, Cn, Dn, Hn, 3);
    krowdiv<<<Cn, 128>>>(pExn, pSn);   // ExnN: rows sum to 1 against Sn

    kgemm<<<dim3(Cn / 64, 2), 256>>>(pFt, proj, nullptr, nullptr, pExt, Cn, Dn, Hn, 3);

    kgemm<<<dim3(Vn / 64, 2), 256>>>(term_emb, proj, nullptr, nullptr, pEle, Vn, Dn, Hn, 3);
    kcolsum<<<256, 128>>>(pEle, Vn, pSe);
    krowdiv<<<Cn, 128>>>(pExt, pSe);   // ExtN

    kstartmlp<<<1, 256>>>(se, sw0, sb0, sw1, sb1, sw2, sb2, sw3, sb3, sw4, sb4, proj);

    // the whole 256-step recursion in ONE launch
    krec<<<NBLK, 256>>>(text, (float*)d_out);
}

// round 16
// speedup vs baseline: 1.3673x; 1.3673x over previous
#include <cuda_runtime.h>
#include <math.h>

#define Cn 4096
#define Vn 32000
#define Hn 256
#define Dn 128
#define Nb 16
#define Tt 256
#define NBLK 128

// ---------------- device scratch (static) ----------------
__device__ float g_t1[Cn * Hn];
__device__ float g_f1[Cn * Hn];
__device__ float g_t2[Cn * Hn];
__device__ float g_ft[Cn * Hn];
__device__ float g_Eyn[Cn * Dn];       // features of next_state_emb
__device__ float g_Exn[Cn * Dn];       // features of state_emb (row-normalized: ExnN·Sn = 1)
__device__ float g_Ext[Cn * Dn];       // features of terminal-MLP out (row-normalized by Se)
__device__ float g_Ele[Vn * Dn];       // features of terminal_emb
__device__ float g_Sn[Dn];
__device__ float g_Se[Dn];
__device__ float g_Exs[Dn];
__device__ float g_buf[3][Nb][Dn];     // rotating G state buffers
__device__ float g_zb[3][Nb];          // rotating z normalizers (z_t in slot t%3)
__device__ unsigned g_flag[NBLK * 8];  // per-block barrier flags (32B stride)

// ---------------- zero / reset ----------------
__global__ __launch_bounds__(256) void kzero() {
    int i = threadIdx.x;
    if (i < Dn) { g_Sn[i] = 0.f; g_Se[i] = 0.f; }
    for (int j = i; j < NBLK * 8; j += 256) g_flag[j] = 0u;
}

// ------------- generic tiled GEMM: Out = epi(A[M,K]@W[K,N]) -------------
// mode 1: relu(+bias); 2: relu(+bias)+R; 3: l2-normalize-A-rows then exp(x-0.5)
__global__ __launch_bounds__(256) void kgemm(const float* __restrict__ A,
                                             const float* __restrict__ W,
                                             const float* __restrict__ bias,
                                             const float* __restrict__ R,
                                             float* __restrict__ Out,
                                             int M, int N, int K, int mode) {
    __shared__ float As[16][68];
    __shared__ float Ws[16][68];
    int tid = threadIdx.x;
    int m0 = blockIdx.x * 64, n0 = blockIdx.y * 64;
    int ar = tid >> 2, ak = (tid & 3) * 4;
    int wk = tid >> 4, wn = (tid & 15) * 4;
    int ty = tid >> 4, tx = tid & 15;
    float acc[4][4] = {};
    float ss[4] = {};   // row sum-of-squares (mode 3)
    for (int kt = 0; kt < K; kt += 16) {
        float4 av = *(const float4*)(A + (size_t)(m0 + ar) * K + kt + ak);
        As[ak + 0][ar] = av.x; As[ak + 1][ar] = av.y;
        As[ak + 2][ar] = av.z; As[ak + 3][ar] = av.w;
        *(float4*)&Ws[wk][wn] = *(const float4*)(W + (size_t)(kt + wk) * N + n0 + wn);
        __syncthreads();
#pragma unroll
        for (int k = 0; k < 16; k++) {
            float a[4], b[4];
            *(float4*)a = *(const float4*)&As[k][ty * 4];
            *(float4*)b = *(const float4*)&Ws[k][tx * 4];
            if (mode == 3) {
#pragma unroll
                for (int i = 0; i < 4; i++) ss[i] += a[i] * a[i];
            }
#pragma unroll
            for (int i = 0; i < 4; i++)
#pragma unroll
                for (int j = 0; j < 4; j++) acc[i][j] += a[i] * b[j];
        }
        __syncthreads();
    }
#pragma unroll
    for (int i = 0; i < 4; i++) {
        int m = m0 + ty * 4 + i;
        float rs = (mode == 3) ? rsqrtf(ss[i]) : 1.f;
#pragma unroll
        for (int j = 0; j < 4; j++) {
            int n = n0 + tx * 4 + j;
            float v = acc[i][j];
            if (mode == 1 || mode == 2) v = fmaxf(v + bias[n], 0.f);
            if (mode == 2) v += R[(size_t)m * N + n];
            if (mode == 3) v = expf(v * rs - 0.5f);
            Out[(size_t)m * N + n] = v;
        }
    }
}

// ------------- column sums -------------
__global__ __launch_bounds__(128) void kcolsum(const float* __restrict__ E, int rows,
                                               float* __restrict__ S) {
    int d = threadIdx.x;
    float acc = 0.f;
    for (int r = blockIdx.x; r < rows; r += gridDim.x) acc += E[(size_t)r * Dn + d];
    atomicAdd(&S[d], acc);
}

// ------------- row normalize: E[r,:] /= (E[r,:]·S) -------------
__global__ __launch_bounds__(128) void krowdiv(float* __restrict__ E,
                                               const float* __restrict__ S) {
    int r = blockIdx.x, tid = threadIdx.x;
    __shared__ float red[4];
    float v = E[(size_t)r * Dn + tid];
    float p = v * S[tid];
#pragma unroll
    for (int o = 16; o; o >>= 1) p += __shfl_xor_sync(~0u, p, o);
    if ((tid & 31) == 0) red[tid >> 5] = p;
    __syncthreads();
    float u = red[0] + red[1] + red[2] + red[3];
    E[(size_t)r * Dn + tid] = v / u;
}

// ------------- start MLP + features of the single start vector -------------
__global__ __launch_bounds__(256) void kstartmlp(
    const float* se, const float* w0, const float* b0,
    const float* w1, const float* b1, const float* w2, const float* b2,
    const float* w3, const float* b3, const float* w4, const float* b4,
    const float* proj) {
    __shared__ float xs[256], Ab[256], Bb[256], Cb[256];
    __shared__ float red[8], sinv;
    int tid = threadIdx.x;
    xs[tid] = se[tid];
    __syncthreads();
    float acc = 0.f;
    for (int i = 0; i < 256; i++) acc += xs[i] * w0[i * 256 + tid];
    Ab[tid] = acc + b0[tid];
    __syncthreads();
    acc = 0.f;
    for (int i = 0; i < 256; i++) acc += Ab[i] * w1[i * 256 + tid];
    Bb[tid] = fmaxf(acc + b1[tid], 0.f);
    __syncthreads();
    acc = 0.f;
    for (int i = 0; i < 256; i++) acc += Bb[i] * w2[i * 256 + tid];
    Cb[tid] = fmaxf(acc + b2[tid], 0.f) + Ab[tid];
    __syncthreads();
    acc = 0.f;
    for (int i = 0; i < 256; i++) acc += Cb[i] * w3[i * 256 + tid];
    __syncthreads();
    Bb[tid] = fmaxf(acc + b3[tid], 0.f);
    __syncthreads();
    acc = 0.f;
    for (int i = 0; i < 256; i++) acc += Bb[i] * w4[i * 256 + tid];
    Ab[tid] = fmaxf(acc + b4[tid], 0.f) + Cb[tid];
    __syncthreads();
    float ss = Ab[tid] * Ab[tid];
#pragma unroll
    for (int o = 16; o; o >>= 1) ss += __shfl_xor_sync(~0u, ss, o);
    if ((tid & 31) == 0) red[tid >> 5] = ss;
    __syncthreads();
    if (tid == 0) {
        float t = 0.f;
        for (int i = 0; i < 8; i++) t += red[i];
        sinv = rsqrtf(t);
    }
    __syncthreads();
    if (tid < 128) {
        float a2 = 0.f;
        for (int i = 0; i < 256; i++) a2 += Ab[i] * proj[i * 128 + tid];
        g_Exs[tid] = expf(a2 * sinv - 0.5f);
    }
}

// =========== persistent recursion kernel: all 256 HMM steps ===========
// One flag barrier per step; G' via RED; z via identity z_{t+1} = sum_c A[:,c].
__global__ __launch_bounds__(256, 1) void krec(const int* __restrict__ text,
                                               float* __restrict__ out) {
    __shared__ float Gs[Nb][Dn];
    __shared__ float Egs[Nb][Dn];
    __shared__ float Ash[Nb][32];
    __shared__ float zsh[Nb];
    int tid = threadIdx.x;
    int blk = blockIdx.x;
    int w = tid >> 5, lane = tid & 31;
    int cl = tid >> 3, q = tid & 7;
    int dd = tid & 127, half = tid >> 7;
    unsigned want = 1;

    // persistent operands: thread owns d-chunks {j*32 + q*4 .. +3} of its state row
    float a[16], b[16], xn[32];
    {
        const float4* ap = (const float4*)(g_Ext + (size_t)(blk * 32 + cl) * Dn + q * 4);
        const float4* bp = (const float4*)(g_Eyn + (size_t)(blk * 32 + cl) * Dn + q * 4);
#pragma unroll
        for (int j = 0; j < 4; j++) {
            *(float4*)&a[j * 4] = ap[j * 8];   // stride 32 floats = 8 float4
            *(float4*)&b[j * 4] = bp[j * 8];
        }
#pragma unroll
        for (int k = 0; k < 32; k++) xn[k] = g_Exn[(size_t)(blk * 32 + k) * Dn + dd];
    }

    // init: buf0 = Exs replicated, buf1 = 0; z0 = Exs·Sn, z-slot1 = 0 (block 0)
    if (tid < 16) {
        int ib = blk * 16 + tid;
        __stcg(&((float*)g_buf[0])[ib], g_Exs[ib & 127]);
        __stcg(&((float*)g_buf[1])[ib], 0.f);
    }
    if (blk == 0) {
        if (w == 0) {
            float4 e4 = *(const float4*)(g_Exs + lane * 4);
            float4 s4 = *(const float4*)(g_Sn + lane * 4);
            float z0 = e4.x * s4.x + e4.y * s4.y + e4.z * s4.z + e4.w * s4.w;
#pragma unroll
            for (int o = 16; o; o >>= 1) z0 += __shfl_xor_sync(~0u, z0, o);
            if (lane < 16) {
                __stcg(&g_zb[0][lane], z0);
                __stcg(&g_zb[1][lane], 0.f);
            }
        }
    }
    float evAcc = 0.f;

    // ---- barrier (init) ----
    __threadfence();
    __syncthreads();
    if (tid == 0) *(volatile unsigned*)&g_flag[blk * 8] = want;
    if (tid < NBLK) {
        volatile unsigned* fl = &g_flag[tid * 8];
        while (*fl < want) {}
    }
    __syncthreads();
    want++;

    // prefetch token features for t=0
    float egv[8];
#pragma unroll
    for (int k = 0; k < 8; k++) {
        int i = k * 256 + tid, n = i >> 7, d = i & 127;
        int tk = __ldg(&text[n * Tt + 0]);
        egv[k] = __ldg(&g_Ele[(size_t)tk * Dn + d]);
    }

    for (int t = 0; t < Tt; t++) {
        const float* Gcur = (const float*)g_buf[t % 3];
        float* Gnext = (float*)g_buf[(t + 1) % 3];
        float* Gz = (float*)g_buf[(t + 2) % 3];
        const float* zcur = g_zb[t % 3];
        float* znext = g_zb[(t + 1) % 3];
        float* zz = g_zb[(t + 2) % 3];

        // z: single-line read (identity z = previous step's A row-sums)
        if (tid < 16) {
            float zr = __ldcg(&zcur[tid]);
            if (blk == 0 && t > 0) evAcc += logf(zr);
            zsh[tid] = 1.f / zr;
        }
        __syncthreads();

        // load G, scale by 1/z, stage (warp w owns batches w and w+8)
        {
            float4 ga = __ldcg((const float4*)(Gcur + w * Dn + lane * 4));
            float4 gb = __ldcg((const float4*)(Gcur + (w + 8) * Dn + lane * 4));
            float ia = zsh[w], ib2 = zsh[w + 8];
            ga.x *= ia; ga.y *= ia; ga.z *= ia; ga.w *= ia;
            gb.x *= ib2; gb.y *= ib2; gb.z *= ib2; gb.w *= ib2;
            *(float4*)&Gs[w][lane * 4] = ga;
            *(float4*)&Gs[w + 8][lane * 4] = gb;
        }
#pragma unroll
        for (int k = 0; k < 8; k++) ((float*)Egs)[k * 256 + tid] = egv[k];
        __syncthreads();

        // A-phase: accumulate ALL 32 dots first (pure FMA, full ILP) ...
        float eo[Nb], mo[Nb];
#pragma unroll
        for (int n = 0; n < Nb; n++) {
            float e0 = 0.f, m0 = 0.f;
#pragma unroll
            for (int j = 0; j < 4; j++) {
                float4 e = *(const float4*)&Egs[n][j * 32 + q * 4];
                float4 g = *(const float4*)&Gs[n][j * 32 + q * 4];
                e0 += a[j*4]*e.x + a[j*4+1]*e.y + a[j*4+2]*e.z + a[j*4+3]*e.w;
                m0 += b[j*4]*g.x + b[j*4+1]*g.y + b[j*4+2]*g.z + b[j*4+3]*g.w;
            }
            eo[n] = e0; mo[n] = m0;
        }
        // ... then batched independent shfl reductions (issue-bound, not latency)
#pragma unroll
        for (int o = 4; o; o >>= 1) {
#pragma unroll
            for (int n = 0; n < Nb; n++) {
                eo[n] += __shfl_xor_sync(~0u, eo[n], o);
                mo[n] += __shfl_xor_sync(~0u, mo[n], o);
            }
        }
        if (q == 0) {
#pragma unroll
            for (int n = 0; n < Nb; n++) Ash[n][cl] = eo[n] * mo[n];
        }
        __syncthreads();

        // z-partial for t+1: znext[n] += sum of this block's A row
        if (tid < 16) {
            float zp = 0.f;
            const float* arow = Ash[tid];
#pragma unroll
            for (int c2 = 0; c2 < 32; c2++) zp += arow[c2];
            atomicAdd(&znext[tid], zp);
        }

        // G'[n,d] += A[n, block slice] @ ExnN[block slice, d]
#pragma unroll
        for (int k = 0; k < 8; k++) {
            int n = 2 * k + half;
            float acc = 0.f;
            const float* arow = Ash[n];
#pragma unroll
            for (int c2 = 0; c2 < 32; c2++) acc += arow[c2] * xn[c2];
            atomicAdd(&Gnext[n * Dn + dd], acc);
        }
        // zero the buffers that become accumulate targets at t+1
        if (tid < 16) __stcg(&Gz[blk * 16 + tid], 0.f);
        if (blk == 0 && tid < 16) __stcg(&zz[tid], 0.f);

        // ---- barrier: arrive, prefetch under the window, tight poll ----
        __threadfence();
        __syncthreads();
        if (tid == 0) *(volatile unsigned*)&g_flag[blk * 8] = want;
        if (t + 1 < Tt) {
#pragma unroll
            for (int k = 0; k < 8; k++) {
                int i = k * 256 + tid, n = i >> 7, d = i & 127;
                int tk = __ldg(&text[n * Tt + t + 1]);
                egv[k] = __ldg(&g_Ele[(size_t)tk * Dn + d]);
            }
        }
        if (tid < NBLK) {
            volatile unsigned* fl = &g_flag[tid * 8];
            while (*fl < want) {}
        }
        __syncthreads();
        want++;
    }

    // finalize: block 0 adds log z_256 (slot 256%3 == 1) and reduces evidence
    if (blk == 0) {
        if (tid < 16) evAcc += logf(__ldcg(&g_zb[Tt % 3][tid]));
        if (w == 0) {
#pragma unroll
            for (int o = 8; o; o >>= 1) evAcc += __shfl_xor_sync(~0u, evAcc, o);
            if (tid == 0) out[0] = evAcc;
        }
    }
}

extern "C" void kernel_launch(void* const* d_in, const int* in_sizes, int n_in,
                              void* d_out, int out_size) {
    (void)n_in; (void)out_size;
    const float *se, *sw0, *sb0, *sw1, *sb1, *sw2, *sb2, *sw3, *sb3, *sw4, *sb4;
    const float *state_emb, *next_state_emb, *pre_emb;
    const float *tw1, *tb1, *tw2, *tb2, *tw3, *tb3, *tw4, *tb4, *term_emb, *proj;
    const int* text;
    if (in_sizes[0] == Hn) {
        se  = (const float*)d_in[0];
        sw0 = (const float*)d_in[1];  sb0 = (const float*)d_in[2];
        sw1 = (const float*)d_in[3];  sb1 = (const float*)d_in[4];
        sw2 = (const float*)d_in[5];  sb2 = (const float*)d_in[6];
        sw3 = (const float*)d_in[7];  sb3 = (const float*)d_in[8];
        sw4 = (const float*)d_in[9];  sb4 = (const float*)d_in[10];
        state_emb = (const float*)d_in[11];
        next_state_emb = (const float*)d_in[12];
        pre_emb = (const float*)d_in[13];
        tw1 = (const float*)d_in[14]; tb1 = (const float*)d_in[15];
        tw2 = (const float*)d_in[16]; tb2 = (const float*)d_in[17];
        tw3 = (const float*)d_in[18]; tb3 = (const float*)d_in[19];
        tw4 = (const float*)d_in[20]; tb4 = (const float*)d_in[21];
        term_emb = (const float*)d_in[22];
        proj = (const float*)d_in[23];
        text = (const int*)d_in[24];
    } else {
        text = (const int*)d_in[0];
        se  = (const float*)d_in[2];
        sw0 = (const float*)d_in[3];  sb0 = (const float*)d_in[4];
        sw1 = (const float*)d_in[5];  sb1 = (const float*)d_in[6];
        sw2 = (const float*)d_in[7];  sb2 = (const float*)d_in[8];
        sw3 = (const float*)d_in[9];  sb3 = (const float*)d_in[10];
        sw4 = (const float*)d_in[11]; sb4 = (const float*)d_in[12];
        tw1 = (const float*)d_in[13]; tb1 = (const float*)d_in[14];
        tw2 = (const float*)d_in[15]; tb2 = (const float*)d_in[16];
        tw3 = (const float*)d_in[17]; tb3 = (const float*)d_in[18];
        tw4 = (const float*)d_in[19]; tb4 = (const float*)d_in[20];
        state_emb = (const float*)d_in[21];
        next_state_emb = (const float*)d_in[22];
        pre_emb = (const float*)d_in[23];
        term_emb = (const float*)d_in[24];
        proj = (const float*)d_in[25];
    }

    float *pT1, *pF1, *pT2, *pFt, *pEyn, *pExn, *pExt, *pEle, *pSn, *pSe;
    cudaGetSymbolAddress((void**)&pT1, g_t1);
    cudaGetSymbolAddress((void**)&pF1, g_f1);
    cudaGetSymbolAddress((void**)&pT2, g_t2);
    cudaGetSymbolAddress((void**)&pFt, g_ft);
    cudaGetSymbolAddress((void**)&pEyn, g_Eyn);
    cudaGetSymbolAddress((void**)&pExn, g_Exn);
    cudaGetSymbolAddress((void**)&pExt, g_Ext);
    cudaGetSymbolAddress((void**)&pEle, g_Ele);
    cudaGetSymbolAddress((void**)&pSn, g_Sn);
    cudaGetSymbolAddress((void**)&pSe, g_Se);

    kzero<<<1, 256>>>();

    // terminal MLP: two ResLayers on preterminal_emb
    kgemm<<<dim3(Cn / 64, 4), 256>>>(pre_emb, tw1, tb1, nullptr, pT1, Cn, Hn, Hn, 1);
    kgemm<<<dim3(Cn / 64, 4), 256>>>(pT1, tw2, tb2, pre_emb, pF1, Cn, Hn, Hn, 2);
    kgemm<<<dim3(Cn / 64, 4), 256>>>(pF1, tw3, tb3, nullptr, pT2, Cn, Hn, Hn, 1);
    kgemm<<<dim3(Cn / 64, 4), 256>>>(pT2, tw4, tb4, pF1, pFt, Cn, Hn, Hn, 2);

    // features (mode 3 = fused row-l2norm + exp(x-0.5))
    kgemm<<<dim3(Cn / 64, 2), 256>>>(next_state_emb, proj, nullptr, nullptr, pEyn, Cn, Dn, Hn, 3);
    kcolsum<<<256, 128>>>(pEyn, Cn, pSn);

    kgemm<<<dim3(Cn / 64, 2), 256>>>(state_emb, proj, nullptr, nullptr, pExn, Cn, Dn, Hn, 3);
    krowdiv<<<Cn, 128>>>(pExn, pSn);   // ExnN: rows sum to 1 against Sn

    kgemm<<<dim3(Cn / 64, 2), 256>>>(pFt, proj, nullptr, nullptr, pExt, Cn, Dn, Hn, 3);

    kgemm<<<dim3(Vn / 64, 2), 256>>>(term_emb, proj, nullptr, nullptr, pEle, Vn, Dn, Hn, 3);
    kcolsum<<<256, 128>>>(pEle, Vn, pSe);
    krowdiv<<<Cn, 128>>>(pExt, pSe);   // ExtN

    kstartmlp<<<1, 256>>>(se, sw0, sb0, sw1, sb1, sw2, sb2, sw3, sb3, sw4, sb4, proj);

    // the whole 256-step recursion in ONE launch
    krec<<<NBLK, 256>>>(text, (float*)d_out);
}